// round 17
// baseline (speedup 1.0000x reference)
#include <cuda_runtime.h>
#include <cuda_bf16.h>
#include <cstdint>
#include <cmath>

#define T_LEN 1024
#define NH    512
#define NI    128
#define BSZ   64
#define DT_C  0.1f

// Hoisted input projection scratch: tanh(x @ x2h), [B, T, H] fp32 (134 MB).
__device__ float g_tanhI[(size_t)BSZ * T_LEN * NH];

typedef unsigned long long ull;

// ---------------------------------------------------------------------------
// helpers
// ---------------------------------------------------------------------------
__device__ __forceinline__ uint32_t smem_u32(const void* p) {
    uint32_t a;
    asm("{ .reg .u64 t; cvta.to.shared.u64 t, %1; cvt.u32.u64 %0, t; }" : "=r"(a) : "l"(p));
    return a;
}
__device__ __forceinline__ uint32_t mapa_sc(uint32_t addr, uint32_t rank) {
    uint32_t r;
    asm("mapa.shared::cluster.u32 %0, %1, %2;" : "=r"(r) : "r"(addr), "r"(rank));
    return r;
}
__device__ __forceinline__ void cluster_sync_() {
    asm volatile("barrier.cluster.arrive.aligned;" ::: "memory");
    asm volatile("barrier.cluster.wait.aligned;" ::: "memory");
}
__device__ __forceinline__ void bar_named(int id, int cnt) {
    asm volatile("bar.sync %0, %1;" :: "r"(id), "r"(cnt) : "memory");
}
__device__ __forceinline__ ull pack2(float w) {
    ull r;
    asm("mov.b64 %0, {%1, %1};" : "=l"(r) : "f"(w));
    return r;
}
__device__ __forceinline__ void unpack2(float& lo, float& hi, ull v) {
    asm("mov.b64 {%0, %1}, %2;" : "=f"(lo), "=f"(hi) : "l"(v));
}
__device__ __forceinline__ void ffma2(ull& d, ull a, ull b) {
    asm("fma.rn.f32x2 %0, %1, %2, %0;" : "+l"(d) : "l"(a), "l"(b));
}
__device__ __forceinline__ void mbar_init(uint32_t addr, uint32_t count) {
    asm volatile("mbarrier.init.shared.b64 [%0], %1;" :: "r"(addr), "r"(count) : "memory");
}
__device__ __forceinline__ void mbar_expect(uint32_t addr, uint32_t bytes) {
    asm volatile("mbarrier.arrive.expect_tx.shared.b64 _, [%0], %1;"
                 :: "r"(addr), "r"(bytes) : "memory");
}
__device__ __forceinline__ void mbar_wait(uint32_t mbar, uint32_t parity) {
    uint32_t done;
    asm volatile(
        "{\n\t.reg .pred p;\n\t"
        "mbarrier.try_wait.parity.acquire.cluster.shared::cta.b64 p, [%1], %2;\n\t"
        "selp.b32 %0, 1, 0, p;\n\t}"
        : "=r"(done) : "r"(mbar), "r"(parity) : "memory");
    if (!done) {
        asm volatile(
            "{\n\t.reg .pred P1;\n\t"
            "W_%=:\n\t"
            "mbarrier.try_wait.parity.acquire.cluster.shared::cta.b64 P1, [%0], %1, 0x989680;\n\t"
            "@P1 bra.uni D_%=;\n\t"
            "bra.uni W_%=;\n\t"
            "D_%=:\n\t}"
            :: "r"(mbar), "r"(parity) : "memory");
    }
}
__device__ __forceinline__ void fence_async_() {
    asm volatile("fence.proxy.async.shared::cta;" ::: "memory");
}
__device__ __forceinline__ void bulk_dsm(uint32_t dst_cluster, uint32_t src_cta,
                                         uint32_t bytes, uint32_t mbar_cluster) {
    asm volatile(
        "cp.async.bulk.shared::cluster.shared::cta.mbarrier::complete_tx::bytes "
        "[%0], [%1], %2, [%3];"
        :: "r"(dst_cluster), "r"(src_cta), "r"(bytes), "r"(mbar_cluster) : "memory");
}

// ---------------------------------------------------------------------------
// Phase 1: g_tanhI[bt, h] = tanh( x[bt, :] @ x2h[:, h] )
// ---------------------------------------------------------------------------
__global__ void __launch_bounds__(256) phase1_kernel(const float* __restrict__ x,
                                                     const float* __restrict__ x2h) {
    __shared__ float  x_s[16 * 132];
    __shared__ float4 w4_s[128 * 16];
    const int tid = threadIdx.x;
    const int bt0 = blockIdx.x * 16;

    for (int i = tid; i < 512; i += 256) {
        int r = i >> 5, c = i & 31;
        float4 v = *reinterpret_cast<const float4*>(x + (size_t)(bt0 + r) * NI + c * 4);
        *reinterpret_cast<float4*>(x_s + r * 132 + c * 4) = v;
    }

    const int tt = tid & 15;
    const int jc = tid >> 4;
    for (int chunk = 0; chunk < 8; ++chunk) {
        __syncthreads();
        const int jbase = chunk * 64;
        for (int i = tid; i < 2048; i += 256) {
            int k = i >> 4, jq = i & 15;
            w4_s[k * 16 + jq] =
                *reinterpret_cast<const float4*>(x2h + (size_t)k * NH + jbase + jq * 4);
        }
        __syncthreads();
        float a0 = 0.f, a1 = 0.f, a2 = 0.f, a3 = 0.f;
        #pragma unroll 8
        for (int k = 0; k < 128; ++k) {
            float  xv = x_s[tt * 132 + k];
            float4 w  = w4_s[k * 16 + jc];
            a0 = fmaf(xv, w.x, a0); a1 = fmaf(xv, w.y, a1);
            a2 = fmaf(xv, w.z, a2); a3 = fmaf(xv, w.w, a3);
        }
        float4 o = make_float4(tanhf(a0), tanhf(a1), tanhf(a2), tanhf(a3));
        *reinterpret_cast<float4*>(g_tanhI + (size_t)(bt0 + tt) * NH + jbase + jc * 4) = o;
    }
}

// ---------------------------------------------------------------------------
// Phase 2: recurrence. 16 clusters x 8 CTAs x 512 threads.
// TWO-GROUP SOFTWARE PIPELINE: group A = batch rows {0,1}, B = {2,3}.
// All warps compute A then B; group A's red flight hides under B's compute,
// hyB hides under next step's A compute. 4 tx-mbarriers (redA/redB/hyA/hyB).
//
// SMEM float layout:
//   [0)      w      64*514 = 32896
//   [32896)  hybA   8*2*64 = 1024   ([rank][m][kl], 512B blocks)
//   [33920)  hybB   1024
//   [34944)  pdA    128 ull = 256   (pre dup [j][m]={p,p})
//   [35200)  pdB    256
//   [35456)  stg    8*64*2 = 1024   ([ks][jg][m0,m1])
//   [36480)  redA   8*2*64 = 1024   ([src][m][kl])
//   [37504)  redB   1024
//   [38528)  rdoA   1024            ([tgt][m][kl])
//   [39552)  rdoB   1024
//   [40576)  hystA  128             ([m][kl])
//   [40704)  hystB  128
//   [40832)  bias   64
//   [40896)  mbars  4 x 8B = 8 floats
//   total 40904 floats = 163616 B
// ---------------------------------------------------------------------------
#define WS        514
#define W_OFF     0
#define HYA_OFF   32896
#define HYB_OFF   33920
#define PDA_OFF   34944
#define PDB_OFF   35200
#define STG_OFF   35456
#define REDA_OFF  36480
#define REDB_OFF  37504
#define RDOA_OFF  38528
#define RDOB_OFF  39552
#define HYSTA_OFF 40576
#define HYSTB_OFF 40704
#define BIAS_OFF  40832
#define MBAR_OFF  40896
#define SMEM_FLOATS 40904
#define SMEM_BYTES  (SMEM_FLOATS * 4)

__global__ void __launch_bounds__(512)
rnn_kernel(const float* __restrict__ h2h, const float* __restrict__ bias,
           const float* __restrict__ gamma_v, const float* __restrict__ eps_v,
           float* __restrict__ out_states, float* __restrict__ out_hy) {
    extern __shared__ float sm[];
    float* bias_s = sm + BIAS_OFF;
    ull*   pdA = reinterpret_cast<ull*>(sm + PDA_OFF);
    ull*   pdB = reinterpret_cast<ull*>(sm + PDB_OFF);

    const int tid = threadIdx.x;
    const int wid = tid >> 5, lid = tid & 31;
    uint32_t rank;
    asm("mov.u32 %0, %%cluster_ctarank;" : "=r"(rank));
    const int m_base = (blockIdx.x >> 3) * 4;
    const int J0 = (int)rank * 64;
    const uint32_t smb = smem_u32(sm);
    const uint32_t redA_mbar = smb + MBAR_OFF * 4;
    const uint32_t redB_mbar = smb + MBAR_OFF * 4 + 8;
    const uint32_t hyA_mbar  = smb + MBAR_OFF * 4 + 16;
    const uint32_t hyB_mbar  = smb + MBAR_OFF * 4 + 24;

    // --- init ---
    for (int idx = tid; idx < 64 * 512; idx += 512) {
        int k = idx >> 6, jl = idx & 63;
        sm[W_OFF + jl * WS + k] = h2h[(size_t)k * NH + J0 + jl];
    }
    if (tid < 64) bias_s[tid] = bias[J0 + tid];
    for (int i = tid; i < 2048; i += 512) sm[HYA_OFF + i] = 0.f;   // hybA + hybB
    if (tid == 0) {
        mbar_init(redA_mbar, 1); mbar_init(redB_mbar, 1);
        mbar_init(hyA_mbar, 1);  mbar_init(hyB_mbar, 1);
        mbar_expect(redA_mbar, 3584);  // 7 peers x 512B, phase 0
        mbar_expect(redB_mbar, 3584);
        mbar_expect(hyA_mbar, 3584);
        mbar_expect(hyB_mbar, 3584);
    }

    // --- thread mappings ---
    const int ks = tid >> 6;          // GEMM1 k-chunk 0..7 (= hyb rank-block)
    const int jg = tid & 63;          // GEMM1 local j
    const int kp = tid >> 1;          // GEMM2 k-pair 0..255
    const int mh = tid & 1;           // GEMM2 m-within-group
    const int m_u  = tid >> 6;        // update (tid<256): m (0,1 = A; 2,3 = B)
    const int kl_u = tid & 63;
    const int k_own = J0 + kl_u;
    const int grp_idx = tid & 127;    // index within group state [m][kl]

    // issuers: warp 8 lanes 0..6 (group A), warp 9 lanes 0..6 (group B)
    const bool issA = (wid == 8 && lid < 7);
    const bool issB = (wid == 9 && lid < 7);
    uint32_t rA_dst = 0, rA_src = 0, rA_mb = 0, hA_dst = 0, hA_src = 0, hA_mb = 0;
    uint32_t rB_dst = 0, rB_src = 0, rB_mb = 0, hB_dst = 0, hB_src = 0, hB_mb = 0;
    if (issA) {
        const uint32_t p = (rank + 1u + (uint32_t)lid) & 7u;
        rA_dst = mapa_sc(smb + REDA_OFF * 4, p) + rank * 512;
        rA_src = smb + RDOA_OFF * 4 + p * 512;
        rA_mb  = mapa_sc(redA_mbar, p);
        hA_dst = mapa_sc(smb + HYA_OFF * 4, p) + rank * 512;
        hA_src = smb + HYSTA_OFF * 4;
        hA_mb  = mapa_sc(hyA_mbar, p);
    }
    if (issB) {
        const uint32_t p = (rank + 1u + (uint32_t)lid) & 7u;
        rB_dst = mapa_sc(smb + REDB_OFF * 4, p) + rank * 512;
        rB_src = smb + RDOB_OFF * 4 + p * 512;
        rB_mb  = mapa_sc(redB_mbar, p);
        hB_dst = mapa_sc(smb + HYB_OFF * 4, p) + rank * 512;
        hB_src = smb + HYSTB_OFF * 4;
        hB_mb  = mapa_sc(hyB_mbar, p);
    }

    float hy_r = 0.f, hz_r = 0.f, g_r = 0.f, e_r = 0.f, tI = 0.f;
    size_t row_base = 0;
    if (tid < 256) {
        g_r = gamma_v[k_own];
        e_r = eps_v[k_own];
        row_base = (size_t)(m_base + m_u) * T_LEN * NH + k_own;
        tI = g_tanhI[row_base];
    }

    __syncthreads();

    // --- GEMM1 weights -> registers (k-pair packed, fully unrolled) ---
    ull wp[32];
    {
        const ull* wsrc = reinterpret_cast<const ull*>(sm + W_OFF + jg * WS + ks * 64);
        #pragma unroll
        for (int i = 0; i < 32; ++i) wp[i] = wsrc[i];
    }

    cluster_sync_();

    const ulonglong2* hbA = reinterpret_cast<const ulonglong2*>(sm + HYA_OFF + ks * 128);
    const ulonglong2* hbB = reinterpret_cast<const ulonglong2*>(sm + HYB_OFF + ks * 128);
    const ull* w2p = reinterpret_cast<const ull*>(sm + W_OFF) + kp;   // stride 257 ull

    for (int t = 0; t < T_LEN; ++t) {
        const uint32_t parT  = (uint32_t)(t & 1);
        const uint32_t parT1 = (uint32_t)((t + 1) & 1);

        // ================= GROUP A compute =================
        if (t) {
            mbar_wait(hyA_mbar, parT1);
            if (tid == 0 && t <= T_LEN - 2) mbar_expect(hyA_mbar, 3584);
        }
        {   // GEMM1(A): 2 m, register weights
            ull a0 = 0, a1 = 0;
            #pragma unroll
            for (int i = 0; i < 16; ++i) {
                ulonglong2 h0 = hbA[i];
                ulonglong2 h1 = hbA[16 + i];
                ffma2(a0, wp[2 * i], h0.x); ffma2(a0, wp[2 * i + 1], h0.y);
                ffma2(a1, wp[2 * i], h1.x); ffma2(a1, wp[2 * i + 1], h1.y);
            }
            float lo, hi; float2 o;
            unpack2(lo, hi, a0); o.x = lo + hi;
            unpack2(lo, hi, a1); o.y = lo + hi;
            *reinterpret_cast<float2*>(sm + STG_OFF + (ks * 64 + jg) * 2) = o;
        }
        __syncthreads();
        if (tid < 128) {                 // reduce A -> pdA (dup)
            const int rj = tid >> 1, rm = tid & 1;
            float s = bias_s[rj];
            #pragma unroll
            for (int q = 0; q < 8; ++q) s += sm[STG_OFF + q * 128 + rj * 2 + rm];
            pdA[rj * 2 + rm] = pack2(tanhf(s));
        }
        __syncthreads();
        {   // GEMM2(A): thread (kp, mh), 1 m
            ull c0 = 0;
            #pragma unroll 16
            for (int j = 0; j < 64; ++j) {
                ull w2 = w2p[j * 257];
                ull pv = pdA[j * 2 + mh];
                ffma2(c0, w2, pv);
            }
            const int tgt = kp >> 5, off = (kp & 31) * 2;
            float* base = (tgt == (int)rank) ? (sm + REDA_OFF + (int)rank * 128)
                                             : (sm + RDOA_OFF + tgt * 128);
            *reinterpret_cast<ull*>(base + mh * 64 + off) = c0;
        }
        __syncthreads();
        if (issA) { fence_async_(); bulk_dsm(rA_dst, rA_src, 512, rA_mb); }

        // ================= GROUP B compute (redA in flight) =================
        if (t) {
            mbar_wait(hyB_mbar, parT1);
            if (tid == 0 && t <= T_LEN - 2) mbar_expect(hyB_mbar, 3584);
        }
        {   // GEMM1(B)
            ull a0 = 0, a1 = 0;
            #pragma unroll
            for (int i = 0; i < 16; ++i) {
                ulonglong2 h0 = hbB[i];
                ulonglong2 h1 = hbB[16 + i];
                ffma2(a0, wp[2 * i], h0.x); ffma2(a0, wp[2 * i + 1], h0.y);
                ffma2(a1, wp[2 * i], h1.x); ffma2(a1, wp[2 * i + 1], h1.y);
            }
            float lo, hi; float2 o;
            unpack2(lo, hi, a0); o.x = lo + hi;
            unpack2(lo, hi, a1); o.y = lo + hi;
            *reinterpret_cast<float2*>(sm + STG_OFF + (ks * 64 + jg) * 2) = o;
        }
        __syncthreads();
        if (tid < 128) {                 // reduce B -> pdB
            const int rj = tid >> 1, rm = tid & 1;
            float s = bias_s[rj];
            #pragma unroll
            for (int q = 0; q < 8; ++q) s += sm[STG_OFF + q * 128 + rj * 2 + rm];
            pdB[rj * 2 + rm] = pack2(tanhf(s));
        }
        __syncthreads();
        {   // GEMM2(B)
            ull c0 = 0;
            #pragma unroll 16
            for (int j = 0; j < 64; ++j) {
                ull w2 = w2p[j * 257];
                ull pv = pdB[j * 2 + mh];
                ffma2(c0, w2, pv);
            }
            const int tgt = kp >> 5, off = (kp & 31) * 2;
            float* base = (tgt == (int)rank) ? (sm + REDB_OFF + (int)rank * 128)
                                             : (sm + RDOB_OFF + tgt * 128);
            *reinterpret_cast<ull*>(base + mh * 64 + off) = c0;
        }
        __syncthreads();
        if (issB) { fence_async_(); bulk_dsm(rB_dst, rB_src, 512, rB_mb); }

        // ================= UPDATE A (warps 0-3) =================
        if (tid < 128) {
            int tn = (t + 1 < T_LEN) ? (t + 1) : (T_LEN - 1);
            float tI_next = g_tanhI[row_base + (size_t)tn * NH];

            mbar_wait(redA_mbar, parT);
            if (tid == 0 && t + 1 < T_LEN) mbar_expect(redA_mbar, 3584);

            float s = 0.f;
            #pragma unroll
            for (int src = 0; src < 8; ++src) s += sm[REDA_OFF + src * 128 + grp_idx];

            hz_r = hz_r + DT_C * (tI - s - g_r * hy_r - e_r * hz_r);
            hy_r = hy_r + DT_C * hz_r;
            tI = tI_next;

            sm[HYSTA_OFF + grp_idx] = hy_r;
            sm[HYA_OFF + (int)rank * 128 + grp_idx] = hy_r;
        }
        if (wid < 4 || wid == 8) {
            bar_named(1, 160);
            if (t + 1 < T_LEN && issA) { fence_async_(); bulk_dsm(hA_dst, hA_src, 512, hA_mb); }
            if (tid < 128)
                out_states[(size_t)(m_base + m_u) * T_LEN * NH + (size_t)t * NH + k_own] = hy_r;
        }

        // ================= UPDATE B (warps 4-7) =================
        if (tid >= 128 && tid < 256) {
            int tn = (t + 1 < T_LEN) ? (t + 1) : (T_LEN - 1);
            float tI_next = g_tanhI[row_base + (size_t)tn * NH];

            mbar_wait(redB_mbar, parT);
            if (tid == 128 && t + 1 < T_LEN) mbar_expect(redB_mbar, 3584);

            float s = 0.f;
            #pragma unroll
            for (int src = 0; src < 8; ++src) s += sm[REDB_OFF + src * 128 + grp_idx];

            hz_r = hz_r + DT_C * (tI - s - g_r * hy_r - e_r * hz_r);
            hy_r = hy_r + DT_C * hz_r;
            tI = tI_next;

            sm[HYSTB_OFF + grp_idx] = hy_r;
            sm[HYB_OFF + (int)rank * 128 + grp_idx] = hy_r;
        }
        if ((wid >= 4 && wid < 8) || wid == 9) {
            bar_named(2, 160);
            if (t + 1 < T_LEN && issB) { fence_async_(); bulk_dsm(hB_dst, hB_src, 512, hB_mb); }
            if (tid >= 128 && tid < 256)
                out_states[(size_t)(m_base + m_u) * T_LEN * NH + (size_t)t * NH + k_own] = hy_r;
        }

        __syncthreads();   // self hyb + stage/pd WAR before next step
    }

    if (tid < 256 && out_hy)
        out_hy[(size_t)(m_base + m_u) * NH + k_own] = hy_r;

    cluster_sync_();   // keep smem alive until all peer traffic settles
}

// ---------------------------------------------------------------------------
extern "C" void kernel_launch(void* const* d_in, const int* in_sizes, int n_in,
                              void* d_out, int out_size) {
    const float* x    = (const float*)d_in[0];
    const float* x2h  = (const float*)d_in[1];
    const float* h2h  = (const float*)d_in[2];
    const float* bias = (const float*)d_in[3];
    const float* gam  = (const float*)d_in[4];
    const float* eps  = (const float*)d_in[5];
    float* out = (float*)d_out;

    const long long BTH = (long long)BSZ * T_LEN * NH;
    float* states = nullptr;
    float* hyout  = nullptr;
    if ((long long)out_size >= BTH) {
        states = out;
        if ((long long)out_size >= BTH + (long long)BSZ * NH) hyout = out + BTH;
    } else {
        hyout = out;
    }

    phase1_kernel<<<(BSZ * T_LEN) / 16, 256>>>(x, x2h);

    cudaFuncSetAttribute(rnn_kernel, cudaFuncAttributeMaxDynamicSharedMemorySize,
                         SMEM_BYTES);

    cudaLaunchConfig_t cfg = {};
    cfg.gridDim = dim3(128, 1, 1);
    cfg.blockDim = dim3(512, 1, 1);
    cfg.dynamicSmemBytes = SMEM_BYTES;
    cfg.stream = 0;
    cudaLaunchAttribute attrs[1];
    attrs[0].id = cudaLaunchAttributeClusterDimension;
    attrs[0].val.clusterDim.x = 8;
    attrs[0].val.clusterDim.y = 1;
    attrs[0].val.clusterDim.z = 1;
    cfg.attrs = attrs;
    cfg.numAttrs = 1;
    cudaLaunchKernelEx(&cfg, rnn_kernel, h2h, bias, gam, eps, states, hyout);
}